// round 14
// baseline (speedup 1.0000x reference)
#include <cuda_runtime.h>
#include <cuda_bf16.h>
#include <cuda_fp8.h>
#include <cstdint>

// Problem dims
#define BB 4
#define SS 2048
#define DD 1024
#define EE 2048
#define NN 16
#define MM (BB*SS)          // 8192 tokens
#define CH 32               // scan chunks per sequence
#define CLEN (SS/CH)        // 64

// ---------------- scratch (device globals; no allocation allowed) ----------
__device__ __align__(256) uint8_t g_xln8[(size_t)MM*DD];         // fp8 ln out
__device__ __align__(256) __nv_bfloat16 g_xpg[(size_t)MM*2*EE];  // x_proj (xp|gate) bf16
__device__ __align__(256) uint8_t g_xc8[(size_t)MM*EE];          // fp8 conv+silu out
__device__ __align__(256) __nv_bfloat16 g_cu [(size_t)MM*EE];    // cc*u (fused gemm1 epilogue)
__device__ __align__(256) __nv_bfloat16 g_xg [(size_t)MM*EE];    // gated ssm out bf16
__device__ __align__(256) uint8_t g_win8[(size_t)2*EE*DD];       // fp8 W_in
__device__ __align__(256) uint8_t g_wcd8[(size_t)2*EE*EE];       // fp8 interleaved W_c/W_d rows
__device__ __align__(256) __nv_bfloat16 g_wout[(size_t)DD*EE];   // bf16 W_out
__device__ float g_a[EE];
__device__ float g_cc[EE];
__device__ float g_biascat[2*EE];   // interleaved: [2f]=b_c[f], [2f+1]=b_d[f]
__device__ float g_ylast[BB*EE*CH];
__device__ float g_yinit[BB*EE*CH];

// ---------------- helpers ----------------
__device__ __forceinline__ uint32_t smem_u32(const void* p){
    return (uint32_t)__cvta_generic_to_shared(p);
}
__device__ __forceinline__ void cp_async16(uint32_t saddr, const void* gptr){
    asm volatile("cp.async.cg.shared.global [%0], [%1], 16;" :: "r"(saddr), "l"(gptr));
}
__device__ __forceinline__ void cp_commit(){ asm volatile("cp.async.commit_group;"); }
__device__ __forceinline__ void ldsm4(uint32_t& r0,uint32_t& r1,uint32_t& r2,uint32_t& r3,uint32_t addr){
    asm volatile("ldmatrix.sync.aligned.m8n8.x4.shared.b16 {%0,%1,%2,%3}, [%4];"
        : "=r"(r0),"=r"(r1),"=r"(r2),"=r"(r3) : "r"(addr));
}
__device__ __forceinline__ void mma_bf16(float* c, uint32_t a0,uint32_t a1,uint32_t a2,uint32_t a3,
                                         uint32_t b0,uint32_t b1){
    asm volatile("mma.sync.aligned.m16n8k16.row.col.f32.bf16.bf16.f32 "
        "{%0,%1,%2,%3},{%4,%5,%6,%7},{%8,%9},{%0,%1,%2,%3};"
        : "+f"(c[0]),"+f"(c[1]),"+f"(c[2]),"+f"(c[3])
        : "r"(a0),"r"(a1),"r"(a2),"r"(a3),"r"(b0),"r"(b1));
}
__device__ __forceinline__ void mma_fp8(float* c, uint32_t a0,uint32_t a1,uint32_t a2,uint32_t a3,
                                        uint32_t b0,uint32_t b1){
    asm volatile("mma.sync.aligned.m16n8k32.row.col.f32.e4m3.e4m3.f32 "
        "{%0,%1,%2,%3},{%4,%5,%6,%7},{%8,%9},{%0,%1,%2,%3};"
        : "+f"(c[0]),"+f"(c[1]),"+f"(c[2]),"+f"(c[3])
        : "r"(a0),"r"(a1),"r"(a2),"r"(a3),"r"(b0),"r"(b1));
}
__device__ __forceinline__ float sigf(float x){ return 1.f/(1.f+__expf(-x)); }
__device__ __forceinline__ uint32_t bf2u(__nv_bfloat162 v){
    uint32_t u; memcpy(&u, &v, 4); return u;
}
__device__ __forceinline__ uint16_t f2fp8x2(float a, float b){
    return (uint16_t)__nv_cvt_float2_to_fp8x2(make_float2(a,b), __NV_SATFINITE, __NV_E4M3);
}
__device__ __forceinline__ uint32_t f4fp8x4(float4 v){
    uint32_t lo = f2fp8x2(v.x, v.y);
    uint32_t hi = f2fp8x2(v.z, v.w);
    return lo | (hi << 16);
}

// ---------------- merged prep ----------------
__global__ void prep_kernel(const float* __restrict__ win, const float* __restrict__ wc,
                            const float* __restrict__ wd, const float* __restrict__ wout,
                            const float* __restrict__ log_delta, const float* __restrict__ Amat,
                            const float* __restrict__ Bmat, const float* __restrict__ bc,
                            const float* __restrict__ bd, const float* __restrict__ x,
                            const float* __restrict__ g, const float* __restrict__ bta){
    int blk = blockIdx.x;
    int tid = threadIdx.x;
    if (blk < 8192){
        int m = blk;
        const float* row = x + (size_t)m*DD;
        float v[4], s=0.f, s2=0.f;
        #pragma unroll
        for (int i=0;i<4;i++){ v[i]=row[tid+i*256]; s+=v[i]; s2+=v[i]*v[i]; }
        #pragma unroll
        for (int o=16;o;o>>=1){ s += __shfl_xor_sync(~0u,s,o); s2 += __shfl_xor_sync(~0u,s2,o); }
        __shared__ float sh[2][8];
        int w = tid>>5, l = tid&31;
        if (l==0){ sh[0][w]=s; sh[1][w]=s2; }
        __syncthreads();
        s=0.f; s2=0.f;
        #pragma unroll
        for (int j=0;j<8;j++){ s+=sh[0][j]; s2+=sh[1][j]; }
        float mu = s*(1.f/DD);
        float var = s2*(1.f/DD) - mu*mu;
        float rs = rsqrtf(var + 1e-5f);
        #pragma unroll
        for (int i=0;i<4;i++){
            int c = tid+i*256;
            float val = (v[i]-mu)*rs*g[c] + bta[c];
            g_xln8[(size_t)m*DD + c] = (uint8_t)__nv_cvt_float_to_fp8(val, __NV_SATFINITE, __NV_E4M3);
        }
    } else if (blk < 12288){
        size_t idx = (size_t)(blk-8192)*256 + tid;
        size_t i4 = idx*4;
        *reinterpret_cast<uint32_t*>(&g_win8[i4]) = f4fp8x4(*reinterpret_cast<const float4*>(&win[i4]));
        {
            size_t f = i4 >> 11;
            size_t k = i4 & 2047;
            *reinterpret_cast<uint32_t*>(&g_wcd8[(2*f)*EE + k])   = f4fp8x4(*reinterpret_cast<const float4*>(&wc[i4]));
            *reinterpret_cast<uint32_t*>(&g_wcd8[(2*f+1)*EE + k]) = f4fp8x4(*reinterpret_cast<const float4*>(&wd[i4]));
        }
        if (i4 < (size_t)DD*EE){
            float4 v = *reinterpret_cast<const float4*>(&wout[i4]);
            uint2 r;
            r.x = bf2u(__floats2bfloat162_rn(v.x, v.y));
            r.y = bf2u(__floats2bfloat162_rn(v.z, v.w));
            *reinterpret_cast<uint2*>(&g_wout[i4]) = r;
        }
    } else {
        int e = (blk-12288)*256 + tid;
        if (e < EE){
            float dl = log_delta[e];
            float sp = (dl > 20.f) ? dl : log1pf(expf(dl));
            g_a[e] = expf(-sp);
            float s = 0.f;
            #pragma unroll
            for (int n=0; n<NN; n++) s += Amat[e*NN+n]*Bmat[e*NN+n];
            g_cc[e] = s;
            g_biascat[2*e]   = bc[e];
            g_biascat[2*e+1] = bd[e];
        }
    }
}

// ---------------- persistent FP8 GEMM, 2 CTAs/SM --------------------------
// BM=128 BN=128, 256 threads (2x4 warps, 64x32 warp tile), 64B K chunks,
// 4-stage cp.async pipeline, persistent tile stream.
// MODE 0: A=g_xln8 (K=1024) B=g_win8 -> g_xpg bf16 (+b_in)
// MODE 1: A=g_xc8  (K=2048) B=g_wcd8 -> g_cu fused cc*(U+bc)*sig(V+bd)
#define SDB 80u
#define A_ST (128u*SDB)                 // 10240
#define B_ST (128u*SDB)                 // 10240
#define STT (A_ST + B_ST)               // 20480
#define FP8_SMEM (4*STT)                // 81920
#define NCTA 296

template<int MODE>
__global__ __launch_bounds__(256,2) void gemm_fp8(const float* __restrict__ bias_p){
    constexpr int K_ = (MODE==0)?1024:2048;
    constexpr int KT = K_/64;            // 16 or 32
    constexpr int KSH = (KT==16)?4:5;
    constexpr int KTM = KT-1;
    constexpr int NTILES = 2048;         // 64 M-tiles x 32 N-tiles
    const uint8_t* A  = (MODE==0)? g_xln8 : g_xc8;
    const uint8_t* Bw = (MODE==0)? g_win8 : g_wcd8;

    extern __shared__ uint8_t smem[];
    const uint32_t sbase = smem_u32(smem);
    const int tid = threadIdx.x, lane = tid & 31, warp = tid >> 5;
    const int wm = warp >> 2, wn = warp & 3;    // 2 x 4 warp grid
    const int bid = blockIdx.x;

    const int nmy = (NTILES - 1 - bid)/NCTA + 1;
    const int qtot = nmy*KT;

    // loader constants: 256 threads cover 64 rows x 64B per pass
    const int l_row0 = tid >> 2, l_seg = (tid & 3) * 16;
    const uint32_t l_sm = (uint32_t)(l_row0*SDB + l_seg);
    // ldsm constants
    const uint32_t rA0 = (uint32_t)((wm*64 + (lane&15))*SDB + (lane>>4)*16);
    const uint32_t rB0 = (uint32_t)((wn*32 + ((lane>>4)<<3) + (lane&7))*SDB + ((lane>>3)&1)*16);

    auto load_chunk = [&](int q){
        if (q < qtot){
            int ti = q >> KSH;
            int kt = q & KTM;
            int t  = bid + ti*NCTA;
            int bm = (t >> 5) * 128, bn = (t & 31) * 128;
            uint32_t a0 = sbase + (uint32_t)(q & 3)*STT;
            const uint8_t* gA = A  + (size_t)bm*K_ + kt*64;
            const uint8_t* gB = Bw + (size_t)bn*K_ + kt*64;
            cp_async16(a0 + l_sm,              gA + (size_t)l_row0*K_ + l_seg);
            cp_async16(a0 + l_sm + 64u*SDB,    gA + (size_t)(l_row0+64)*K_ + l_seg);
            cp_async16(a0 + A_ST + l_sm,           gB + (size_t)l_row0*K_ + l_seg);
            cp_async16(a0 + A_ST + l_sm + 64u*SDB, gB + (size_t)(l_row0+64)*K_ + l_seg);
        }
        cp_commit();
    };

    float acc[4][4][4];
    #pragma unroll
    for (int i=0;i<4;i++) for (int j=0;j<4;j++) for (int q=0;q<4;q++) acc[i][j][q]=0.f;

    load_chunk(0); load_chunk(1); load_chunk(2);

    for (int q=0; q<qtot; q++){
        asm volatile("cp.async.wait_group 2;" ::: "memory");
        __syncthreads();
        load_chunk(q+3);

        uint32_t baseA = sbase + (uint32_t)(q & 3)*STT;
        uint32_t baseB = baseA + A_ST;
        uint32_t afr[2][4][4], bfr[2][2][4];
        #pragma unroll
        for (int p=0;p<2;p++){
            int cb = p*32;
            #pragma unroll
            for (int i=0;i<4;i++){
                ldsm4(afr[p][i][0],afr[p][i][1],afr[p][i][2],afr[p][i][3],
                      baseA + rA0 + (uint32_t)(i*16)*SDB + cb);
            }
            #pragma unroll
            for (int jp=0;jp<2;jp++){
                ldsm4(bfr[p][jp][0],bfr[p][jp][1],bfr[p][jp][2],bfr[p][jp][3],
                      baseB + rB0 + (uint32_t)(jp*16)*SDB + cb);
            }
        }
        #pragma unroll
        for (int p=0;p<2;p++){
            #pragma unroll
            for (int i=0;i<4;i++){
                #pragma unroll
                for (int j=0;j<4;j++){
                    int jp=j>>1, o=(j&1)*2;
                    mma_fp8(acc[i][j], afr[p][i][0],afr[p][i][1],afr[p][i][2],afr[p][i][3],
                            bfr[p][jp][o], bfr[p][jp][o+1]);
                }
            }
        }

        if ((q & KTM) == KTM){
            int ti = q >> KSH;
            int t  = bid + ti*NCTA;
            int bm = (t >> 5) * 128, bn = (t & 31) * 128;
            const int ro = lane >> 2, co = (lane & 3) * 2;
            #pragma unroll
            for (int i=0;i<4;i++){
                #pragma unroll
                for (int j=0;j<4;j++){
                    int r  = bm + wm*64 + i*16 + ro;
                    int cc = bn + wn*32 + j*8 + co;
                    if (MODE == 0){
                        float b0 = bias_p[cc], b1 = bias_p[cc+1];
                        *reinterpret_cast<__nv_bfloat162*>(&g_xpg[(size_t)r*4096 + cc])
                            = __floats2bfloat162_rn(acc[i][j][0]+b0, acc[i][j][1]+b1);
                        *reinterpret_cast<__nv_bfloat162*>(&g_xpg[(size_t)(r+8)*4096 + cc])
                            = __floats2bfloat162_rn(acc[i][j][2]+b0, acc[i][j][3]+b1);
                    } else {
                        float b0 = g_biascat[cc], b1 = g_biascat[cc+1];
                        int f = cc >> 1;
                        float cf = g_cc[f];
                        float u0 = cf * (acc[i][j][0]+b0) * sigf(acc[i][j][1]+b1);
                        float u1 = cf * (acc[i][j][2]+b0) * sigf(acc[i][j][3]+b1);
                        g_cu[(size_t)r*EE + f]     = __float2bfloat16(u0);
                        g_cu[(size_t)(r+8)*EE + f] = __float2bfloat16(u1);
                    }
                    acc[i][j][0]=0.f; acc[i][j][1]=0.f; acc[i][j][2]=0.f; acc[i][j][3]=0.f;
                }
            }
        }
    }
}

// ---------------- bf16 GEMM (out): out = xg @ W_out^T + b + resid ----------
#define SD 72u
#define A_STAGE_B (256u*SD*2u)
#define B_STAGE_B (128u*SD*2u)
#define STAGE_TOT (A_STAGE_B + B_STAGE_B)
#define BF16_SMEM (3*STAGE_TOT)          // 165888

__global__ __launch_bounds__(512,1) void gemm_out(const float* __restrict__ bias_p,
                                                  const float* __restrict__ resid,
                                                  float* __restrict__ outf){
    constexpr int N_ = 1024;
    constexpr int K_ = 2048;
    constexpr int KT = K_/64;
    const __nv_bfloat16* A  = g_xg;
    const __nv_bfloat16* Bw = g_wout;

    extern __shared__ uint8_t smemb[];
    const uint32_t sbase = smem_u32(smemb);

    const int tid = threadIdx.x;
    const int lane = tid & 31, warp = tid >> 5;
    const int wm = warp >> 2, wn = warp & 3;
    const int bm = blockIdx.y * 256, bn = blockIdx.x * 128;

    float acc[4][4][4];
    #pragma unroll
    for (int i=0;i<4;i++) for (int j=0;j<4;j++) for (int q=0;q<4;q++) acc[i][j][q]=0.f;

    auto load_tile = [&](int kt, int s){
        uint32_t a0 = sbase + (uint32_t)s*STAGE_TOT;
        uint32_t b0 = a0 + A_STAGE_B;
        #pragma unroll
        for (int h=0; h<4; h++){
            int c = tid + h*512;
            int row = c >> 3, seg = (c & 7) * 8;
            cp_async16(a0 + (uint32_t)((row*SD + seg)*2),
                       A + (size_t)(bm+row)*K_ + kt*64 + seg);
        }
        #pragma unroll
        for (int h=0; h<2; h++){
            int c = tid + h*512;
            int row = c >> 3, seg = (c & 7) * 8;
            cp_async16(b0 + (uint32_t)((row*SD + seg)*2),
                       Bw + (size_t)(bn+row)*K_ + kt*64 + seg);
        }
        cp_commit();
    };

    const int la_row = lane & 15;
    const int la_c8  = (lane >> 4) << 3;
    const int lb_row = ((lane >> 4) << 3) + (lane & 7);
    const int lb_c8  = ((lane >> 3) & 1) << 3;

    load_tile(0,0); load_tile(1,1);

    for (int kt=0; kt<KT; kt++){
        if (KT-1-kt >= 1) { asm volatile("cp.async.wait_group 1;" ::: "memory"); }
        else              { asm volatile("cp.async.wait_group 0;" ::: "memory"); }
        __syncthreads();
        if (kt+2 < KT) load_tile(kt+2, (kt+2)%3);

        uint32_t baseA = sbase + (uint32_t)(kt%3)*STAGE_TOT;
        uint32_t baseB = baseA + A_STAGE_B;
        #pragma unroll
        for (int k16=0;k16<4;k16++){
            int kb = k16*16;
            uint32_t a[4][4], bfr[2][4];
            #pragma unroll
            for (int i=0;i<4;i++){
                uint32_t ad = baseA + (uint32_t)(((wm*64 + i*16 + la_row)*SD + kb + la_c8)*2);
                ldsm4(a[i][0],a[i][1],a[i][2],a[i][3], ad);
            }
            #pragma unroll
            for (int jp=0;jp<2;jp++){
                uint32_t bd = baseB + (uint32_t)(((wn*32 + jp*16 + lb_row)*SD + kb + lb_c8)*2);
                ldsm4(bfr[jp][0],bfr[jp][1],bfr[jp][2],bfr[jp][3], bd);
            }
            #pragma unroll
            for (int i=0;i<4;i++){
                #pragma unroll
                for (int j=0;j<4;j++){
                    int jp=j>>1, o=(j&1)*2;
                    mma_bf16(acc[i][j], a[i][0],a[i][1],a[i][2],a[i][3], bfr[jp][o], bfr[jp][o+1]);
                }
            }
        }
    }

    const int ro = lane >> 2, co = (lane & 3) * 2;
    #pragma unroll
    for (int i=0;i<4;i++){
        #pragma unroll
        for (int j=0;j<4;j++){
            int r  = bm + wm*64 + i*16 + ro;
            int cc = bn + wn*32 + j*8 + co;
            float b0 = bias_p[cc], b1 = bias_p[cc+1];
            size_t o0 = (size_t)r*N_ + cc;
            size_t o1 = (size_t)(r+8)*N_ + cc;
            outf[o0]   = acc[i][j][0]+b0 + resid[o0];
            outf[o0+1] = acc[i][j][1]+b1 + resid[o0+1];
            outf[o1]   = acc[i][j][2]+b0 + resid[o1];
            outf[o1+1] = acc[i][j][3]+b1 + resid[o1+1];
        }
    }
}

// ---------------- causal depthwise conv K=4 + silu -> fp8 ----------------
__global__ void conv_kernel(const float* __restrict__ cw, const float* __restrict__ cb){
    int id = blockIdx.x*blockDim.x + threadIdx.x;     // 65536
    int ep = id & 1023;
    int c  = (id >> 10) & 15;
    int b  = id >> 14;
    int e  = ep*2;
    float w[4][2];
    #pragma unroll
    for (int k=0;k<4;k++){ w[k][0]=cw[e*4+k]; w[k][1]=cw[(e+1)*4+k]; }
    float bi0 = cb[e], bi1 = cb[e+1];
    const __nv_bfloat162* XP = reinterpret_cast<const __nv_bfloat162*>(g_xpg);
    uint16_t* XC = reinterpret_cast<uint16_t*>(g_xc8);
    int s0 = c*128;
    float2 win[3];
    #pragma unroll
    for (int k=0;k<3;k++){
        int s = s0 - 3 + k;
        if (s >= 0){
            __nv_bfloat162 t = XP[((size_t)(b*SS+s)*(2*EE) + e) >> 1];
            win[k] = make_float2(__low2float(t), __high2float(t));
        } else win[k] = make_float2(0.f, 0.f);
    }
    #pragma unroll 4
    for (int s=s0; s<s0+128; s++){
        __nv_bfloat162 t = XP[((size_t)(b*SS+s)*(2*EE) + e) >> 1];
        float2 cur = make_float2(__low2float(t), __high2float(t));
        float ax = bi0 + w[0][0]*win[0].x + w[1][0]*win[1].x + w[2][0]*win[2].x + w[3][0]*cur.x;
        float ay = bi1 + w[0][1]*win[0].y + w[1][1]*win[1].y + w[2][1]*win[2].y + w[3][1]*cur.y;
        ax = ax * sigf(ax);
        ay = ay * sigf(ay);
        XC[((size_t)(b*SS+s)*EE + e) >> 1] = f2fp8x2(ax, ay);
        win[0]=win[1]; win[1]=win[2]; win[2]=cur;
    }
}

// ---------------- chunked linear scan (CH=32 chunks of 64) ----------------
__global__ void scanA_kernel(){
    int id = blockIdx.x*blockDim.x + threadIdx.x;   // 131072
    int ep = id & 1023, c = (id >> 10) & (CH-1), b = id >> 15;
    int e = ep*2;
    float a0 = g_a[e], a1 = g_a[e+1];
    float y0 = 0.f, y1 = 0.f;
    size_t tok0 = (size_t)b*SS + c*CLEN;
    const __nv_bfloat162* Up = (const __nv_bfloat162*)g_cu + ((tok0*EE + e) >> 1);
    #pragma unroll 4
    for (int t=0;t<CLEN;t++){
        float2 uv = __bfloat1622float2(Up[(size_t)t*(EE/2)]);
        y0 = a0*y0 + uv.x;
        y1 = a1*y1 + uv.y;
    }
    g_ylast[(((size_t)b<<11)+e)*CH + c]   = y0;
    g_ylast[(((size_t)b<<11)+e+1)*CH + c] = y1;
}
__global__ void scanB_kernel(){
    int id = blockIdx.x*blockDim.x + threadIdx.x;   // 8192
    int e = id & 2047;
    float a = g_a[e];
    float aL = a;
    #pragma unroll
    for (int i=0;i<6;i++) aL *= aL;  // a^64
    float y = 0.f;
    #pragma unroll
    for (int c=0;c<CH;c++){
        g_yinit[id*CH + c] = y;
        y = g_ylast[id*CH + c] + aL*y;
    }
}
__global__ void scanC_kernel(){
    int id = blockIdx.x*blockDim.x + threadIdx.x;   // 131072
    int ep = id & 1023, c = (id >> 10) & (CH-1), b = id >> 15;
    int e = ep*2;
    float a0 = g_a[e], a1 = g_a[e+1];
    float y0 = g_yinit[(((size_t)b<<11)+e)*CH + c];
    float y1 = g_yinit[(((size_t)b<<11)+e+1)*CH + c];
    size_t tok0 = (size_t)b*SS + c*CLEN;
    const __nv_bfloat162* up = (const __nv_bfloat162*)g_cu + ((tok0*EE + e) >> 1);
    const __nv_bfloat162* gp = (const __nv_bfloat162*)g_xpg + ((tok0*(2*EE) + EE + e) >> 1);
    __nv_bfloat162* og = (__nv_bfloat162*)g_xg + ((tok0*EE + e) >> 1);
    #pragma unroll 4
    for (int t=0;t<CLEN;t++){
        float2 uv = __bfloat1622float2(up[(size_t)t*(EE/2)]);
        float2 gv = __bfloat1622float2(gp[(size_t)t*(2*EE/2)]);
        y0 = a0*y0 + uv.x;
        y1 = a1*y1 + uv.y;
        og[(size_t)t*(EE/2)] = __floats2bfloat162_rn(y0*sigf(gv.x), y1*sigf(gv.y));
    }
}

// ---------------- launch ----------------
extern "C" void kernel_launch(void* const* d_in, const int* in_sizes, int n_in,
                              void* d_out, int out_size){
    const float* x         = (const float*)d_in[0];
    const float* ln_g      = (const float*)d_in[1];
    const float* ln_b      = (const float*)d_in[2];
    const float* W_in      = (const float*)d_in[3];
    const float* b_in      = (const float*)d_in[4];
    const float* conv_w    = (const float*)d_in[5];
    const float* conv_b    = (const float*)d_in[6];
    const float* Amat      = (const float*)d_in[7];
    const float* Bmat      = (const float*)d_in[8];
    const float* W_c       = (const float*)d_in[9];
    const float* b_c       = (const float*)d_in[10];
    const float* W_d       = (const float*)d_in[11];
    const float* b_d       = (const float*)d_in[12];
    const float* log_delta = (const float*)d_in[13];
    const float* W_out     = (const float*)d_in[14];
    const float* b_out     = (const float*)d_in[15];
    float* out = (float*)d_out;

    cudaFuncSetAttribute(gemm_fp8<0>, cudaFuncAttributeMaxDynamicSharedMemorySize, FP8_SMEM);
    cudaFuncSetAttribute(gemm_fp8<1>, cudaFuncAttributeMaxDynamicSharedMemorySize, FP8_SMEM);
    cudaFuncSetAttribute(gemm_out, cudaFuncAttributeMaxDynamicSharedMemorySize, BF16_SMEM);

    prep_kernel<<<12296, 256>>>(W_in, W_c, W_d, W_out, log_delta, Amat, Bmat,
                                b_c, b_d, x, ln_g, ln_b);
    gemm_fp8<0><<<NCTA, 256, FP8_SMEM>>>(b_in);
    conv_kernel<<<256, 256>>>(conv_w, conv_b);
    gemm_fp8<1><<<NCTA, 256, FP8_SMEM>>>(nullptr);
    scanA_kernel<<<512, 256>>>();
    scanB_kernel<<<32, 256>>>();
    scanC_kernel<<<512, 256>>>();
    gemm_out<<<dim3(8,32), 512, BF16_SMEM>>>(b_out, x, out);
}

// round 15
// speedup vs baseline: 1.0632x; 1.0632x over previous
#include <cuda_runtime.h>
#include <cuda_bf16.h>
#include <cuda_fp8.h>
#include <cstdint>

// Problem dims
#define BB 4
#define SS 2048
#define DD 1024
#define EE 2048
#define NN 16
#define MM (BB*SS)          // 8192 tokens
#define CH 32               // scan chunks per sequence
#define CLEN (SS/CH)        // 64

// ---------------- scratch (device globals; no allocation allowed) ----------
__device__ __align__(256) uint8_t g_xln8[(size_t)MM*DD];         // fp8 ln out
__device__ __align__(256) __nv_bfloat16 g_xpg[(size_t)MM*2*EE];  // x_proj (xp|gate) bf16
__device__ __align__(256) uint8_t g_xc8[(size_t)MM*EE];          // fp8 conv+silu out
__device__ __align__(256) __nv_bfloat16 g_cu [(size_t)MM*EE];    // cc*u (fused gemm1 epilogue)
__device__ __align__(256) __nv_bfloat16 g_xg [(size_t)MM*EE];    // gated ssm out bf16
__device__ __align__(256) uint8_t g_win8[(size_t)2*EE*DD];       // fp8 W_in
__device__ __align__(256) uint8_t g_wcd8[(size_t)2*EE*EE];       // fp8 interleaved W_c/W_d rows
__device__ __align__(256) __nv_bfloat16 g_wout[(size_t)DD*EE];   // bf16 W_out
__device__ float g_a[EE];
__device__ float g_cc[EE];
__device__ float g_biascat[2*EE];   // interleaved: [2f]=b_c[f], [2f+1]=b_d[f]
__device__ float g_ylast[BB*EE*CH];
__device__ float g_yinit[BB*EE*CH];

// ---------------- helpers ----------------
__device__ __forceinline__ uint32_t smem_u32(const void* p){
    return (uint32_t)__cvta_generic_to_shared(p);
}
__device__ __forceinline__ void cp_async16(uint32_t saddr, const void* gptr){
    asm volatile("cp.async.cg.shared.global [%0], [%1], 16;" :: "r"(saddr), "l"(gptr));
}
__device__ __forceinline__ void cp_commit(){ asm volatile("cp.async.commit_group;"); }
__device__ __forceinline__ void ldsm4(uint32_t& r0,uint32_t& r1,uint32_t& r2,uint32_t& r3,uint32_t addr){
    asm volatile("ldmatrix.sync.aligned.m8n8.x4.shared.b16 {%0,%1,%2,%3}, [%4];"
        : "=r"(r0),"=r"(r1),"=r"(r2),"=r"(r3) : "r"(addr));
}
__device__ __forceinline__ void mma_bf16(float* c, uint32_t a0,uint32_t a1,uint32_t a2,uint32_t a3,
                                         uint32_t b0,uint32_t b1){
    asm volatile("mma.sync.aligned.m16n8k16.row.col.f32.bf16.bf16.f32 "
        "{%0,%1,%2,%3},{%4,%5,%6,%7},{%8,%9},{%0,%1,%2,%3};"
        : "+f"(c[0]),"+f"(c[1]),"+f"(c[2]),"+f"(c[3])
        : "r"(a0),"r"(a1),"r"(a2),"r"(a3),"r"(b0),"r"(b1));
}
__device__ __forceinline__ void mma_fp8(float* c, uint32_t a0,uint32_t a1,uint32_t a2,uint32_t a3,
                                        uint32_t b0,uint32_t b1){
    asm volatile("mma.sync.aligned.m16n8k32.row.col.f32.e4m3.e4m3.f32 "
        "{%0,%1,%2,%3},{%4,%5,%6,%7},{%8,%9},{%0,%1,%2,%3};"
        : "+f"(c[0]),"+f"(c[1]),"+f"(c[2]),"+f"(c[3])
        : "r"(a0),"r"(a1),"r"(a2),"r"(a3),"r"(b0),"r"(b1));
}
__device__ __forceinline__ float sigf(float x){ return 1.f/(1.f+__expf(-x)); }
__device__ __forceinline__ uint32_t bf2u(__nv_bfloat162 v){
    uint32_t u; memcpy(&u, &v, 4); return u;
}
__device__ __forceinline__ uint16_t f2fp8x2(float a, float b){
    return (uint16_t)__nv_cvt_float2_to_fp8x2(make_float2(a,b), __NV_SATFINITE, __NV_E4M3);
}
__device__ __forceinline__ uint32_t f4fp8x4(float4 v){
    uint32_t lo = f2fp8x2(v.x, v.y);
    uint32_t hi = f2fp8x2(v.z, v.w);
    return lo | (hi << 16);
}

// ---------------- merged prep ----------------
__global__ void prep_kernel(const float* __restrict__ win, const float* __restrict__ wc,
                            const float* __restrict__ wd, const float* __restrict__ wout,
                            const float* __restrict__ log_delta, const float* __restrict__ Amat,
                            const float* __restrict__ Bmat, const float* __restrict__ bc,
                            const float* __restrict__ bd, const float* __restrict__ x,
                            const float* __restrict__ g, const float* __restrict__ bta){
    int blk = blockIdx.x;
    int tid = threadIdx.x;
    if (blk < 8192){
        int m = blk;
        const float* row = x + (size_t)m*DD;
        float v[4], s=0.f, s2=0.f;
        #pragma unroll
        for (int i=0;i<4;i++){ v[i]=row[tid+i*256]; s+=v[i]; s2+=v[i]*v[i]; }
        #pragma unroll
        for (int o=16;o;o>>=1){ s += __shfl_xor_sync(~0u,s,o); s2 += __shfl_xor_sync(~0u,s2,o); }
        __shared__ float sh[2][8];
        int w = tid>>5, l = tid&31;
        if (l==0){ sh[0][w]=s; sh[1][w]=s2; }
        __syncthreads();
        s=0.f; s2=0.f;
        #pragma unroll
        for (int j=0;j<8;j++){ s+=sh[0][j]; s2+=sh[1][j]; }
        float mu = s*(1.f/DD);
        float var = s2*(1.f/DD) - mu*mu;
        float rs = rsqrtf(var + 1e-5f);
        #pragma unroll
        for (int i=0;i<4;i++){
            int c = tid+i*256;
            float val = (v[i]-mu)*rs*g[c] + bta[c];
            g_xln8[(size_t)m*DD + c] = (uint8_t)__nv_cvt_float_to_fp8(val, __NV_SATFINITE, __NV_E4M3);
        }
    } else if (blk < 12288){
        size_t idx = (size_t)(blk-8192)*256 + tid;
        size_t i4 = idx*4;
        *reinterpret_cast<uint32_t*>(&g_win8[i4]) = f4fp8x4(*reinterpret_cast<const float4*>(&win[i4]));
        {
            size_t f = i4 >> 11;
            size_t k = i4 & 2047;
            *reinterpret_cast<uint32_t*>(&g_wcd8[(2*f)*EE + k])   = f4fp8x4(*reinterpret_cast<const float4*>(&wc[i4]));
            *reinterpret_cast<uint32_t*>(&g_wcd8[(2*f+1)*EE + k]) = f4fp8x4(*reinterpret_cast<const float4*>(&wd[i4]));
        }
        if (i4 < (size_t)DD*EE){
            float4 v = *reinterpret_cast<const float4*>(&wout[i4]);
            uint2 r;
            r.x = bf2u(__floats2bfloat162_rn(v.x, v.y));
            r.y = bf2u(__floats2bfloat162_rn(v.z, v.w));
            *reinterpret_cast<uint2*>(&g_wout[i4]) = r;
        }
    } else {
        int e = (blk-12288)*256 + tid;
        if (e < EE){
            float dl = log_delta[e];
            float sp = (dl > 20.f) ? dl : log1pf(expf(dl));
            g_a[e] = expf(-sp);
            float s = 0.f;
            #pragma unroll
            for (int n=0; n<NN; n++) s += Amat[e*NN+n]*Bmat[e*NN+n];
            g_cc[e] = s;
            g_biascat[2*e]   = bc[e];
            g_biascat[2*e+1] = bd[e];
        }
    }
}

// ---------------- unified persistent GEMM ----------------------------------
// BM=128 BN=128, 256 threads (2x4 warps, 64x32 warp tile), 128-BYTE K chunks,
// 3-stage cp.async pipeline, 2 CTAs/SM, fragment double-buffer over the 4
// 32-byte k-steps per chunk. fp8 (k32) and bf16 (k16) use byte-identical
// fragment addressing; only the mma opcode differs.
// MODE 0: fp8  A=g_xln8 (1024B rows) B=g_win8 -> g_xpg bf16 (+b_in)
// MODE 1: fp8  A=g_xc8  (2048B rows) B=g_wcd8 -> g_cu fused cc*(U+bc)*sig(V+bd)
// MODE 2: bf16 A=g_xg   (4096B rows) B=g_wout -> fp32 out (+b_out +resid)
#define SDB 144u                        // padded row stride (bytes), 128B chunk + 16B pad
#define A_ST (128u*SDB)                 // 18432
#define STT (2u*A_ST)                   // 36864
#define GEMM_SMEM (3*STT)               // 110592
#define NCTA 296

template<int MODE>
__global__ __launch_bounds__(256,2) void gemm_uni(const float* __restrict__ bias_p,
                                                  const float* __restrict__ resid,
                                                  float* __restrict__ outf){
    constexpr int KB = (MODE==0)?1024:(MODE==1)?2048:4096;  // row length in BYTES
    constexpr int CHK = KB/128;          // chunks per tile: 8 / 16 / 32
    constexpr int CSH = (CHK==8)?3:(CHK==16)?4:5;
    constexpr int CMK = CHK-1;
    constexpr int NTN = (MODE==2)?8:32;  // N tiles
    constexpr int NTSH = (MODE==2)?3:5;
    constexpr int NTILES = 64*NTN;
    const uint8_t* A  = (MODE==0)? g_xln8 : (MODE==1)? g_xc8 : (const uint8_t*)g_xg;
    const uint8_t* Bw = (MODE==0)? g_win8 : (MODE==1)? g_wcd8 : (const uint8_t*)g_wout;

    extern __shared__ uint8_t smem[];
    const uint32_t sbase = smem_u32(smem);
    const int tid = threadIdx.x, lane = tid & 31, warp = tid >> 5;
    const int wm = warp >> 2, wn = warp & 3;    // 2 x 4 warp grid
    const int bid = blockIdx.x;

    const int nmy = (NTILES - 1 - bid)/NCTA + 1;
    const int qtot = nmy*CHK;

    // loader constants: 256 threads x 4 passes cover 128 rows x 8 segs(16B)
    const int l_row0 = tid >> 3, l_seg = (tid & 7) * 16;
    const uint32_t l_sm = (uint32_t)(l_row0*SDB + l_seg);
    // ldsm constants (byte-based; identical for fp8 and bf16)
    const uint32_t rA0 = (uint32_t)((wm*64 + (lane&15))*SDB + (lane>>4)*16);
    const uint32_t rB0 = (uint32_t)((wn*32 + ((lane>>4)<<3) + (lane&7))*SDB + ((lane>>3)&1)*16);

    auto load_chunk = [&](int q){
        if (q < qtot){
            int ti = q >> CSH;
            int kt = q & CMK;
            int t  = bid + ti*NCTA;
            int bm = (t >> NTSH) * 128, bn = (t & (NTN-1)) * 128;
            uint32_t a0 = sbase + (uint32_t)(q % 3)*STT;
            const uint8_t* gA = A  + (size_t)bm*KB + kt*128;
            const uint8_t* gB = Bw + (size_t)bn*KB + kt*128;
            #pragma unroll
            for (int h=0; h<4; h++){
                uint32_t so = l_sm + (uint32_t)(h*32)*SDB;
                size_t go = (size_t)(l_row0 + h*32)*KB + l_seg;
                cp_async16(a0 + so,        gA + go);
                cp_async16(a0 + A_ST + so, gB + go);
            }
        }
        cp_commit();
    };

    float acc[4][4][4];
    #pragma unroll
    for (int i=0;i<4;i++) for (int j=0;j<4;j++) for (int q=0;q<4;q++) acc[i][j][q]=0.f;

    uint32_t afr[2][4][4], bfr[2][2][4];

    load_chunk(0); load_chunk(1);

    for (int q=0; q<qtot; q++){
        asm volatile("cp.async.wait_group 1;" ::: "memory");
        __syncthreads();
        load_chunk(q+2);

        uint32_t baseA = sbase + (uint32_t)(q % 3)*STT;
        uint32_t baseB = baseA + A_ST;

        // load fragments for step 0
        #pragma unroll
        for (int i=0;i<4;i++)
            ldsm4(afr[0][i][0],afr[0][i][1],afr[0][i][2],afr[0][i][3],
                  baseA + rA0 + (uint32_t)(i*16)*SDB);
        #pragma unroll
        for (int jp=0;jp<2;jp++)
            ldsm4(bfr[0][jp][0],bfr[0][jp][1],bfr[0][jp][2],bfr[0][jp][3],
                  baseB + rB0 + (uint32_t)(jp*16)*SDB);

        #pragma unroll
        for (int p=0;p<4;p++){
            int cur = p & 1, nxt = cur ^ 1;
            if (p < 3){
                int cb = (p+1)*32;
                #pragma unroll
                for (int i=0;i<4;i++)
                    ldsm4(afr[nxt][i][0],afr[nxt][i][1],afr[nxt][i][2],afr[nxt][i][3],
                          baseA + rA0 + (uint32_t)(i*16)*SDB + cb);
                #pragma unroll
                for (int jp=0;jp<2;jp++)
                    ldsm4(bfr[nxt][jp][0],bfr[nxt][jp][1],bfr[nxt][jp][2],bfr[nxt][jp][3],
                          baseB + rB0 + (uint32_t)(jp*16)*SDB + cb);
            }
            #pragma unroll
            for (int i=0;i<4;i++){
                #pragma unroll
                for (int j=0;j<4;j++){
                    int jp=j>>1, o=(j&1)*2;
                    if (MODE==2)
                        mma_bf16(acc[i][j], afr[cur][i][0],afr[cur][i][1],afr[cur][i][2],afr[cur][i][3],
                                 bfr[cur][jp][o], bfr[cur][jp][o+1]);
                    else
                        mma_fp8(acc[i][j], afr[cur][i][0],afr[cur][i][1],afr[cur][i][2],afr[cur][i][3],
                                bfr[cur][jp][o], bfr[cur][jp][o+1]);
                }
            }
        }

        if ((q & CMK) == CMK){
            int ti = q >> CSH;
            int t  = bid + ti*NCTA;
            int bm = (t >> NTSH) * 128, bn = (t & (NTN-1)) * 128;
            const int ro = lane >> 2, co = (lane & 3) * 2;
            #pragma unroll
            for (int i=0;i<4;i++){
                #pragma unroll
                for (int j=0;j<4;j++){
                    int r  = bm + wm*64 + i*16 + ro;
                    int cc = bn + wn*32 + j*8 + co;
                    if (MODE == 0){
                        float b0 = bias_p[cc], b1 = bias_p[cc+1];
                        *reinterpret_cast<__nv_bfloat162*>(&g_xpg[(size_t)r*4096 + cc])
                            = __floats2bfloat162_rn(acc[i][j][0]+b0, acc[i][j][1]+b1);
                        *reinterpret_cast<__nv_bfloat162*>(&g_xpg[(size_t)(r+8)*4096 + cc])
                            = __floats2bfloat162_rn(acc[i][j][2]+b0, acc[i][j][3]+b1);
                    } else if (MODE == 1){
                        float b0 = g_biascat[cc], b1 = g_biascat[cc+1];
                        int f = cc >> 1;
                        float cf = g_cc[f];
                        float u0 = cf * (acc[i][j][0]+b0) * sigf(acc[i][j][1]+b1);
                        float u1 = cf * (acc[i][j][2]+b0) * sigf(acc[i][j][3]+b1);
                        g_cu[(size_t)r*EE + f]     = __float2bfloat16(u0);
                        g_cu[(size_t)(r+8)*EE + f] = __float2bfloat16(u1);
                    } else {
                        float b0 = bias_p[cc], b1 = bias_p[cc+1];
                        size_t o0 = (size_t)r*1024 + cc;
                        size_t o1 = (size_t)(r+8)*1024 + cc;
                        outf[o0]   = acc[i][j][0]+b0 + resid[o0];
                        outf[o0+1] = acc[i][j][1]+b1 + resid[o0+1];
                        outf[o1]   = acc[i][j][2]+b0 + resid[o1];
                        outf[o1+1] = acc[i][j][3]+b1 + resid[o1+1];
                    }
                    acc[i][j][0]=0.f; acc[i][j][1]=0.f; acc[i][j][2]=0.f; acc[i][j][3]=0.f;
                }
            }
        }
    }
}

// ---------------- causal depthwise conv K=4 + silu -> fp8 ----------------
__global__ void conv_kernel(const float* __restrict__ cw, const float* __restrict__ cb){
    int id = blockIdx.x*blockDim.x + threadIdx.x;     // 65536
    int ep = id & 1023;
    int c  = (id >> 10) & 15;
    int b  = id >> 14;
    int e  = ep*2;
    float w[4][2];
    #pragma unroll
    for (int k=0;k<4;k++){ w[k][0]=cw[e*4+k]; w[k][1]=cw[(e+1)*4+k]; }
    float bi0 = cb[e], bi1 = cb[e+1];
    const __nv_bfloat162* XP = reinterpret_cast<const __nv_bfloat162*>(g_xpg);
    uint16_t* XC = reinterpret_cast<uint16_t*>(g_xc8);
    int s0 = c*128;
    float2 win[3];
    #pragma unroll
    for (int k=0;k<3;k++){
        int s = s0 - 3 + k;
        if (s >= 0){
            __nv_bfloat162 t = XP[((size_t)(b*SS+s)*(2*EE) + e) >> 1];
            win[k] = make_float2(__low2float(t), __high2float(t));
        } else win[k] = make_float2(0.f, 0.f);
    }
    #pragma unroll 4
    for (int s=s0; s<s0+128; s++){
        __nv_bfloat162 t = XP[((size_t)(b*SS+s)*(2*EE) + e) >> 1];
        float2 cur = make_float2(__low2float(t), __high2float(t));
        float ax = bi0 + w[0][0]*win[0].x + w[1][0]*win[1].x + w[2][0]*win[2].x + w[3][0]*cur.x;
        float ay = bi1 + w[0][1]*win[0].y + w[1][1]*win[1].y + w[2][1]*win[2].y + w[3][1]*cur.y;
        ax = ax * sigf(ax);
        ay = ay * sigf(ay);
        XC[((size_t)(b*SS+s)*EE + e) >> 1] = f2fp8x2(ax, ay);
        win[0]=win[1]; win[1]=win[2]; win[2]=cur;
    }
}

// ---------------- chunked linear scan (CH=32 chunks of 64) ----------------
__global__ void scanA_kernel(){
    int id = blockIdx.x*blockDim.x + threadIdx.x;   // 131072
    int ep = id & 1023, c = (id >> 10) & (CH-1), b = id >> 15;
    int e = ep*2;
    float a0 = g_a[e], a1 = g_a[e+1];
    float y0 = 0.f, y1 = 0.f;
    size_t tok0 = (size_t)b*SS + c*CLEN;
    const __nv_bfloat162* Up = (const __nv_bfloat162*)g_cu + ((tok0*EE + e) >> 1);
    #pragma unroll 4
    for (int t=0;t<CLEN;t++){
        float2 uv = __bfloat1622float2(Up[(size_t)t*(EE/2)]);
        y0 = a0*y0 + uv.x;
        y1 = a1*y1 + uv.y;
    }
    g_ylast[(((size_t)b<<11)+e)*CH + c]   = y0;
    g_ylast[(((size_t)b<<11)+e+1)*CH + c] = y1;
}
__global__ void scanB_kernel(){
    int id = blockIdx.x*blockDim.x + threadIdx.x;   // 8192
    int e = id & 2047;
    float a = g_a[e];
    float aL = a;
    #pragma unroll
    for (int i=0;i<6;i++) aL *= aL;  // a^64
    float y = 0.f;
    #pragma unroll
    for (int c=0;c<CH;c++){
        g_yinit[id*CH + c] = y;
        y = g_ylast[id*CH + c] + aL*y;
    }
}
__global__ void scanC_kernel(){
    int id = blockIdx.x*blockDim.x + threadIdx.x;   // 131072
    int ep = id & 1023, c = (id >> 10) & (CH-1), b = id >> 15;
    int e = ep*2;
    float a0 = g_a[e], a1 = g_a[e+1];
    float y0 = g_yinit[(((size_t)b<<11)+e)*CH + c];
    float y1 = g_yinit[(((size_t)b<<11)+e+1)*CH + c];
    size_t tok0 = (size_t)b*SS + c*CLEN;
    const __nv_bfloat162* up = (const __nv_bfloat162*)g_cu + ((tok0*EE + e) >> 1);
    const __nv_bfloat162* gp = (const __nv_bfloat162*)g_xpg + ((tok0*(2*EE) + EE + e) >> 1);
    __nv_bfloat162* og = (__nv_bfloat162*)g_xg + ((tok0*EE + e) >> 1);
    #pragma unroll 4
    for (int t=0;t<CLEN;t++){
        float2 uv = __bfloat1622float2(up[(size_t)t*(EE/2)]);
        float2 gv = __bfloat1622float2(gp[(size_t)t*(2*EE/2)]);
        y0 = a0*y0 + uv.x;
        y1 = a1*y1 + uv.y;
        og[(size_t)t*(EE/2)] = __floats2bfloat162_rn(y0*sigf(gv.x), y1*sigf(gv.y));
    }
}

// ---------------- launch ----------------
extern "C" void kernel_launch(void* const* d_in, const int* in_sizes, int n_in,
                              void* d_out, int out_size){
    const float* x         = (const float*)d_in[0];
    const float* ln_g      = (const float*)d_in[1];
    const float* ln_b      = (const float*)d_in[2];
    const float* W_in      = (const float*)d_in[3];
    const float* b_in      = (const float*)d_in[4];
    const float* conv_w    = (const float*)d_in[5];
    const float* conv_b    = (const float*)d_in[6];
    const float* Amat      = (const float*)d_in[7];
    const float* Bmat      = (const float*)d_in[8];
    const float* W_c       = (const float*)d_in[9];
    const float* b_c       = (const float*)d_in[10];
    const float* W_d       = (const float*)d_in[11];
    const float* b_d       = (const float*)d_in[12];
    const float* log_delta = (const float*)d_in[13];
    const float* W_out     = (const float*)d_in[14];
    const float* b_out     = (const float*)d_in[15];
    float* out = (float*)d_out;

    cudaFuncSetAttribute(gemm_uni<0>, cudaFuncAttributeMaxDynamicSharedMemorySize, GEMM_SMEM);
    cudaFuncSetAttribute(gemm_uni<1>, cudaFuncAttributeMaxDynamicSharedMemorySize, GEMM_SMEM);
    cudaFuncSetAttribute(gemm_uni<2>, cudaFuncAttributeMaxDynamicSharedMemorySize, GEMM_SMEM);

    prep_kernel<<<12296, 256>>>(W_in, W_c, W_d, W_out, log_delta, Amat, Bmat,
                                b_c, b_d, x, ln_g, ln_b);
    gemm_uni<0><<<NCTA, 256, GEMM_SMEM>>>(b_in, nullptr, nullptr);
    conv_kernel<<<256, 256>>>(conv_w, conv_b);
    gemm_uni<1><<<NCTA, 256, GEMM_SMEM>>>(nullptr, nullptr, nullptr);
    scanA_kernel<<<512, 256>>>();
    scanB_kernel<<<32, 256>>>();
    scanC_kernel<<<512, 256>>>();
    gemm_uni<2><<<NCTA, 256, GEMM_SMEM>>>(b_out, x, out);
}